// round 1
// baseline (speedup 1.0000x reference)
#include <cuda_runtime.h>
#include <cstddef>

// Problem dims (fixed by the reference)
#define BATCH   256
#define SEQ     64
#define INPUT   512
#define HIDDEN  1024
#define CLASSES 1000
#define SB      (SEQ * BATCH)   // 16384
#define G4      (4 * HIDDEN)    // 4096

// ---------------------------------------------------------------------------
// Scratch (device globals — no allocations allowed)
// ---------------------------------------------------------------------------
__device__ float g_X [SB * INPUT];                     //  33.5 MB packed [S*B, I]
__device__ float g_Z [(size_t)SB * G4];                // 268   MB pre-activations (reused by both layers)
__device__ float g_H1[(SEQ + 1) * BATCH * HIDDEN];     //  68   MB h1 per step (slot 0 = zeros)
__device__ float g_G [BATCH * G4];                     //   4   MB per-step gate buffer
__device__ float g_c1[BATCH * HIDDEN];
__device__ float g_c2[BATCH * HIDDEN];
__device__ float g_h2[BATCH * HIDDEN];

// ---------------------------------------------------------------------------
// Pack x: [B, S, I] -> [S*B, I]   (row m = t*B + b)
// ---------------------------------------------------------------------------
__global__ void pack_x_kernel(const float4* __restrict__ x, float4* __restrict__ xp) {
    int n = blockIdx.x * blockDim.x + threadIdx.x;     // over SB*INPUT/4
    const int I4 = INPUT / 4;
    int k = n % I4;
    int r = n / I4;            // r = t*B + b
    int b = r % BATCH;
    int t = r / BATCH;
    xp[n] = x[((size_t)b * SEQ + t) * I4 + k];
}

// ---------------------------------------------------------------------------
// Zero the recurrent state (h1 slot 0, c1, c2, h2)
// ---------------------------------------------------------------------------
__global__ void zero_state_kernel(float* __restrict__ h1_0, float* __restrict__ c1,
                                  float* __restrict__ c2, float* __restrict__ h2) {
    int idx = blockIdx.x * blockDim.x + threadIdx.x;
    if (idx < BATCH * HIDDEN) {
        h1_0[idx] = 0.f; c1[idx] = 0.f; c2[idx] = 0.f; h2[idx] = 0.f;
    }
}

// ---------------------------------------------------------------------------
// Tiled SGEMM: C[M,N] = A[M,K] @ B[K,N] (+ bias[N]) (+ D[M,N])
// Row-major everywhere. 256 threads. BM/TM * BN/TN == 256.
// ---------------------------------------------------------------------------
template<int BM, int BN, int BK, int TM, int TN, bool HAS_BIAS, bool ADD_D, bool GUARD_N>
__global__ void sgemm_kernel(int M, int N, int K,
                             const float* __restrict__ A,
                             const float* __restrict__ B,
                             const float* __restrict__ bias,
                             const float* __restrict__ D,
                             float* __restrict__ C)
{
    constexpr int TX = BN / TN;
    constexpr int TY = BM / TM;
    constexpr int NT = TX * TY;
    static_assert(NT == 256, "need 256 threads");
    constexpr int LA = BM * BK / (NT * 4);   // float4 A loads per thread
    constexpr int LB = BN * BK / (NT * 4);   // float4 B loads per thread
    static_assert(LA >= 1 && LB >= 1, "tile too small");

    __shared__ float As[BK][BM];
    __shared__ float Bs[BK][BN];

    const int tid  = threadIdx.x;
    const int tx   = tid % TX;
    const int ty   = tid / TX;
    const int brow = blockIdx.y * BM;
    const int bcol = blockIdx.x * BN;

    float acc[TM][TN] = {};

    for (int kt = 0; kt < K; kt += BK) {
        // --- load A tile (transposed into As[k][m]) ---
        #pragma unroll
        for (int i = 0; i < LA; i++) {
            int idx = tid + i * NT;
            int ar  = idx / (BK / 4);
            int ak  = (idx % (BK / 4)) * 4;
            float4 v = *reinterpret_cast<const float4*>(
                A + (size_t)(brow + ar) * K + kt + ak);
            As[ak + 0][ar] = v.x;
            As[ak + 1][ar] = v.y;
            As[ak + 2][ar] = v.z;
            As[ak + 3][ar] = v.w;
        }
        // --- load B tile ---
        #pragma unroll
        for (int i = 0; i < LB; i++) {
            int idx = tid + i * NT;
            int bk  = idx / (BN / 4);
            int bn  = (idx % (BN / 4)) * 4;
            if (GUARD_N) {
                int col = bcol + bn;
                const float* src = B + (size_t)(kt + bk) * N + col;
                Bs[bk][bn + 0] = (col + 0 < N) ? src[0] : 0.f;
                Bs[bk][bn + 1] = (col + 1 < N) ? src[1] : 0.f;
                Bs[bk][bn + 2] = (col + 2 < N) ? src[2] : 0.f;
                Bs[bk][bn + 3] = (col + 3 < N) ? src[3] : 0.f;
            } else {
                *reinterpret_cast<float4*>(&Bs[bk][bn]) =
                    *reinterpret_cast<const float4*>(B + (size_t)(kt + bk) * N + bcol + bn);
            }
        }
        __syncthreads();

        #pragma unroll
        for (int k = 0; k < BK; k++) {
            float ra[TM], rb[TN];
            #pragma unroll
            for (int i = 0; i < TM; i++) ra[i] = As[k][ty * TM + i];
            #pragma unroll
            for (int j = 0; j < TN; j++) rb[j] = Bs[k][tx * TN + j];
            #pragma unroll
            for (int i = 0; i < TM; i++)
                #pragma unroll
                for (int j = 0; j < TN; j++)
                    acc[i][j] += ra[i] * rb[j];
        }
        __syncthreads();
    }

    // --- epilogue ---
    #pragma unroll
    for (int i = 0; i < TM; i++) {
        int row = brow + ty * TM + i;
        #pragma unroll
        for (int j = 0; j < TN; j++) {
            int col = bcol + tx * TN + j;
            if (GUARD_N && col >= N) continue;
            float v = acc[i][j];
            if (HAS_BIAS) v += bias[col];
            if (ADD_D)    v += D[(size_t)row * N + col];
            C[(size_t)row * N + col] = v;
        }
    }
}

// ---------------------------------------------------------------------------
// LSTM cell: gates G[B,4H] (i|f|g|o), updates c in place, writes h
// ---------------------------------------------------------------------------
__device__ __forceinline__ float sigmoidf_(float x) { return 1.f / (1.f + expf(-x)); }

__global__ void lstm_cell_kernel(const float* __restrict__ Gt,
                                 float* __restrict__ c,
                                 float* __restrict__ h)
{
    int idx = blockIdx.x * blockDim.x + threadIdx.x;   // over B*H
    int b = idx >> 10;          // H = 1024
    int j = idx & (HIDDEN - 1);
    const float* gb = Gt + (size_t)b * G4;
    float zi = gb[j];
    float zf = gb[HIDDEN + j];
    float zg = gb[2 * HIDDEN + j];
    float zo = gb[3 * HIDDEN + j];
    float cn = sigmoidf_(zf) * c[idx] + sigmoidf_(zi) * tanhf(zg);
    c[idx] = cn;
    h[idx] = sigmoidf_(zo) * tanhf(cn);
}

// ---------------------------------------------------------------------------
// Launch
// ---------------------------------------------------------------------------
extern "C" void kernel_launch(void* const* d_in, const int* in_sizes, int n_in,
                              void* d_out, int out_size)
{
    const float* x  = (const float*)d_in[0];
    const float* W1 = (const float*)d_in[1];
    const float* U1 = (const float*)d_in[2];
    const float* b1 = (const float*)d_in[3];
    const float* W2 = (const float*)d_in[4];
    const float* U2 = (const float*)d_in[5];
    const float* b2 = (const float*)d_in[6];
    const float* Wo = (const float*)d_in[7];
    const float* bo = (const float*)d_in[8];
    float* out = (float*)d_out;

    float *X, *Z, *H1, *G, *c1, *c2, *h2;
    cudaGetSymbolAddress((void**)&X,  g_X);
    cudaGetSymbolAddress((void**)&Z,  g_Z);
    cudaGetSymbolAddress((void**)&H1, g_H1);
    cudaGetSymbolAddress((void**)&G,  g_G);
    cudaGetSymbolAddress((void**)&c1, g_c1);
    cudaGetSymbolAddress((void**)&c2, g_c2);
    cudaGetSymbolAddress((void**)&h2, g_h2);

    const size_t BH  = (size_t)BATCH * HIDDEN;   // 262144
    const size_t BG4 = (size_t)BATCH * G4;       // 1048576

    // 0) pack X + zero state
    {
        int n4 = SB * INPUT / 4;
        pack_x_kernel<<<n4 / 256, 256>>>((const float4*)x, (float4*)X);
        zero_state_kernel<<<(int)(BH / 256), 256>>>(H1, c1, c2, h2);
    }

    // 1) Z = X @ W1 + b1      [16384, 4096], K=512
    {
        dim3 grid(G4 / 128, SB / 128);
        sgemm_kernel<128,128,16,8,8,true,false,false><<<grid, 256>>>(
            SB, G4, INPUT, X, W1, b1, nullptr, Z);
    }

    // 2) layer-1 recurrence
    for (int t = 0; t < SEQ; t++) {
        dim3 grid(G4 / 64, BATCH / 64);   // 64 x 4 = 256 CTAs
        sgemm_kernel<64,64,16,4,4,false,true,false><<<grid, 256>>>(
            BATCH, G4, HIDDEN,
            H1 + (size_t)t * BH,          // h_{t-1}  (slot t; slot 0 = zeros)
            U1, nullptr,
            Z + (size_t)t * BG4,          // precomputed x@W1 + b1 for step t
            G);
        lstm_cell_kernel<<<(int)(BH / 256), 256>>>(G, c1, H1 + (size_t)(t + 1) * BH);
    }

    // 3) Z = H1[1..64] @ W2 + b2   [16384, 4096], K=1024
    {
        dim3 grid(G4 / 128, SB / 128);
        sgemm_kernel<128,128,16,8,8,true,false,false><<<grid, 256>>>(
            SB, G4, HIDDEN, H1 + BH, W2, b2, nullptr, Z);
    }

    // 4) layer-2 recurrence
    for (int t = 0; t < SEQ; t++) {
        dim3 grid(G4 / 64, BATCH / 64);
        sgemm_kernel<64,64,16,4,4,false,true,false><<<grid, 256>>>(
            BATCH, G4, HIDDEN,
            h2, U2, nullptr,
            Z + (size_t)t * BG4,
            G);
        lstm_cell_kernel<<<(int)(BH / 256), 256>>>(G, c2, h2);
    }

    // 5) out = h2 @ Wo + bo    [256, 1000], K=1024
    {
        dim3 grid((CLASSES + 63) / 64, BATCH / 64);
        sgemm_kernel<64,64,16,4,4,true,false,true><<<grid, 256>>>(
            BATCH, CLASSES, HIDDEN, h2, Wo, bo, nullptr, out);
    }
}

// round 3
// speedup vs baseline: 2.6718x; 2.6718x over previous
#include <cuda_runtime.h>
#include <cstdint>
#include <cstddef>

#define BATCH   256
#define SEQ     64
#define INPUT   512
#define HIDDEN  1024
#define CLASSES 1000
#define SB      (SEQ * BATCH)   // 16384
#define G4      (4 * HIDDEN)    // 4096

// ---------------------------------------------------------------------------
// Scratch (device globals — no allocations allowed)
// ---------------------------------------------------------------------------
__device__ float g_X  [SB * INPUT];                    // packed [S*B, I], tf32-rounded
__device__ float g_Z  [(size_t)SB * G4];               // pre-activations (reused by both layers)
__device__ float g_H1 [(SEQ + 1) * BATCH * HIDDEN];    // h1 per step (slot 0 = zeros), tf32
__device__ float g_h2 [2 * BATCH * HIDDEN];            // double-buffered layer-2 h, tf32
__device__ float g_c1 [BATCH * HIDDEN];
__device__ float g_c2 [BATCH * HIDDEN];
__device__ float g_W1r[(size_t)G4 * INPUT];            // W1^T gate-interleaved [4096, 512]
__device__ float g_U1T[(size_t)G4 * HIDDEN];           // U1^T gate-interleaved [4096, 1024]
__device__ float g_W2r[(size_t)G4 * HIDDEN];
__device__ float g_U2T[(size_t)G4 * HIDDEN];
__device__ float g_b1r[G4];
__device__ float g_b2r[G4];

// ---------------------------------------------------------------------------
// Helpers
// ---------------------------------------------------------------------------
__device__ __forceinline__ uint32_t smem_to_u32(const void* p) {
    uint32_t a;
    asm("{ .reg .u64 t; cvta.to.shared.u64 t, %1; cvt.u32.u64 %0, t; }"
        : "=r"(a) : "l"(p));
    return a;
}

__device__ __forceinline__ float to_tf32(float x) {
    uint32_t r;
    asm("cvt.rna.tf32.f32 %0, %1;" : "=r"(r) : "f"(x));
    return __uint_as_float(r);
}

__device__ __forceinline__ void cp_async16(uint32_t smem_dst, const void* gmem_src) {
    asm volatile("cp.async.cg.shared.global [%0], [%1], 16;\n" :: "r"(smem_dst), "l"(gmem_src));
}

__device__ __forceinline__ void mma_tf32_16n8k8(float* d, const uint32_t* a, const uint32_t* b) {
    asm volatile(
        "mma.sync.aligned.m16n8k8.row.col.f32.tf32.tf32.f32 "
        "{%0,%1,%2,%3}, {%4,%5,%6,%7}, {%8,%9}, {%0,%1,%2,%3};"
        : "+f"(d[0]), "+f"(d[1]), "+f"(d[2]), "+f"(d[3])
        : "r"(a[0]), "r"(a[1]), "r"(a[2]), "r"(a[3]), "r"(b[0]), "r"(b[1]));
}

__device__ __forceinline__ float sigf(float x) { return 1.f / (1.f + expf(-x)); }

// ---------------------------------------------------------------------------
// Warp-MMA tf32 GEMM:  C[M,N] = A[M,K] @ Bt[N,K]^T
// Block tile BM x BN, 8 warps (2x4), BK=32, 2-stage cp.async pipeline.
// MODE 0: P0[row*G4+col] = acc + aux[col]          (bias epilogue, writes Z)
// MODE 1: LSTM cell: gates = acc + aux[row*G4+col] (gate-interleaved i,f,g,o);
//         c (P0, [row*H+j]) updated in place; h -> P1 tf32-rounded.
// ---------------------------------------------------------------------------
template<int BM, int BN, int KT, int MODE>
__global__ void __launch_bounds__(256)
mma_gemm(const float* __restrict__ A, int lda,
         const float* __restrict__ Bt,
         const float* __restrict__ aux,
         float* __restrict__ P0,
         float* __restrict__ P1)
{
    constexpr int BK  = 32;
    constexpr int PAD = 36;                // floats per smem row (32 + 4 pad)
    constexpr int WM  = BM / 2;            // warp tile M (2 warp rows)
    constexpr int WN  = BN / 4;            // warp tile N (4 warp cols)
    constexpr int MT  = WM / 16;           // mma tiles per warp (M)
    constexpr int NT  = WN / 8;            // mma tiles per warp (N)
    constexpr int ASZ = BM * PAD;          // floats
    constexpr int BSZ = BN * PAD;

    extern __shared__ float sm[];
    const uint32_t sbase = smem_to_u32(sm);

    const int tid  = threadIdx.x;
    const int wid  = tid >> 5;
    const int lane = tid & 31;
    const int wm0  = (wid >> 2) * WM;
    const int wn0  = (wid & 3) * WN;
    const int m0   = blockIdx.y * BM;
    const int n0   = blockIdx.x * BN;
    const int K    = KT * BK;

    float acc[MT][NT][4] = {};

    // ---- stage loader ----
    auto load_stage = [&](int kt, int s) {
        const uint32_t aB = sbase + (uint32_t)s * (ASZ + BSZ) * 4u;
        const uint32_t bB = aB + (uint32_t)ASZ * 4u;
        const float* Ag = A  + (size_t)m0 * lda + kt * BK;
        const float* Bg = Bt + (size_t)n0 * K   + kt * BK;
        #pragma unroll
        for (int i = 0; i < BM * 8 / 256; i++) {
            int cid = tid + i * 256;
            int row = cid >> 3, c = cid & 7;
            cp_async16(aB + (uint32_t)row * (PAD * 4) + c * 16,
                       Ag + (size_t)row * lda + c * 4);
        }
        #pragma unroll
        for (int i = 0; i < BN * 8 / 256; i++) {
            int cid = tid + i * 256;
            int row = cid >> 3, c = cid & 7;
            cp_async16(bB + (uint32_t)row * (PAD * 4) + c * 16,
                       Bg + (size_t)row * K + c * 4);
        }
        asm volatile("cp.async.commit_group;\n");
    };

    const int r  = lane >> 2;
    const int cq = lane & 3;

    load_stage(0, 0);

    #pragma unroll 1
    for (int kt = 0; kt < KT; kt++) {
        const int s = kt & 1;
        if (kt + 1 < KT) {
            load_stage(kt + 1, s ^ 1);
            asm volatile("cp.async.wait_group 1;\n");
        } else {
            asm volatile("cp.async.wait_group 0;\n");
        }
        __syncthreads();

        const float* as_f = sm + s * (ASZ + BSZ);
        const float* bs_f = as_f + ASZ;

        #pragma unroll
        for (int ks = 0; ks < 4; ks++) {
            const int k0 = ks * 8;
            uint32_t af[MT][4], bf[NT][2];
            #pragma unroll
            for (int mt = 0; mt < MT; mt++) {
                const int rr = wm0 + mt * 16 + r;
                af[mt][0] = __float_as_uint(as_f[rr * PAD + k0 + cq]);
                af[mt][1] = __float_as_uint(as_f[(rr + 8) * PAD + k0 + cq]);
                af[mt][2] = __float_as_uint(as_f[rr * PAD + k0 + cq + 4]);
                af[mt][3] = __float_as_uint(as_f[(rr + 8) * PAD + k0 + cq + 4]);
            }
            #pragma unroll
            for (int nt = 0; nt < NT; nt++) {
                const int cc = wn0 + nt * 8 + r;
                bf[nt][0] = __float_as_uint(bs_f[cc * PAD + k0 + cq]);
                bf[nt][1] = __float_as_uint(bs_f[cc * PAD + k0 + cq + 4]);
            }
            #pragma unroll
            for (int mt = 0; mt < MT; mt++)
                #pragma unroll
                for (int nt = 0; nt < NT; nt++)
                    mma_tf32_16n8k8(acc[mt][nt], af[mt], bf[nt]);
        }
        __syncthreads();
    }

    // ---- epilogue ----
    #pragma unroll
    for (int mt = 0; mt < MT; mt++) {
        #pragma unroll
        for (int nt = 0; nt < NT; nt++) {
            const int row  = m0 + wm0 + mt * 16 + r;
            const int colb = n0 + wn0 + nt * 8 + cq * 2;
            float v0 = acc[mt][nt][0], v1 = acc[mt][nt][1];
            float v2 = acc[mt][nt][2], v3 = acc[mt][nt][3];
            if (MODE == 0) {
                float2 bv = *reinterpret_cast<const float2*>(aux + colb);
                float2 o01 = { v0 + bv.x, v1 + bv.y };
                float2 o23 = { v2 + bv.x, v3 + bv.y };
                *reinterpret_cast<float2*>(P0 + (size_t)row * G4 + colb)       = o01;
                *reinterpret_cast<float2*>(P0 + (size_t)(row + 8) * G4 + colb) = o23;
            } else {
                // add precomputed Z, then assemble (i,f,g,o) quads via shfl
                float2 z01 = *reinterpret_cast<const float2*>(aux + (size_t)row * G4 + colb);
                float2 z23 = *reinterpret_cast<const float2*>(aux + (size_t)(row + 8) * G4 + colb);
                v0 += z01.x; v1 += z01.y; v2 += z23.x; v3 += z23.y;
                // lanes with (lane&1)==0 hold (i,f); partner lane^1 holds (g,o)
                float p0 = __shfl_xor_sync(0xffffffffu, v0, 1);
                float p1 = __shfl_xor_sync(0xffffffffu, v1, 1);
                float p2 = __shfl_xor_sync(0xffffffffu, v2, 1);
                float p3 = __shfl_xor_sync(0xffffffffu, v3, 1);
                if ((lane & 1) == 0) {
                    const int j = colb >> 2;     // colb % 4 == 0 here
                    {   // row
                        const size_t ci = (size_t)row * HIDDEN + j;
                        float cn = sigf(v1) * P0[ci] + sigf(v0) * tanhf(p0);
                        P0[ci] = cn;
                        P1[ci] = to_tf32(sigf(p1) * tanhf(cn));
                    }
                    {   // row + 8
                        const size_t ci = (size_t)(row + 8) * HIDDEN + j;
                        float cn = sigf(v3) * P0[ci] + sigf(v2) * tanhf(p2);
                        P0[ci] = cn;
                        P1[ci] = to_tf32(sigf(p3) * tanhf(cn));
                    }
                }
            }
        }
    }
}

// ---------------------------------------------------------------------------
// Weight transpose + gate interleave: out[4j+g, k] = in[k, g*H + j] (tf32-rounded)
// ---------------------------------------------------------------------------
__global__ void reorder_T_kernel(const float* __restrict__ in, float* __restrict__ out, int K) {
    __shared__ float tile[32][33];
    const int g  = blockIdx.z;
    const int j0 = blockIdx.y * 32;
    const int k0 = blockIdx.x * 32;
    const int tx = threadIdx.x, ty = threadIdx.y;
    tile[ty][tx] = in[(size_t)(k0 + ty) * G4 + g * HIDDEN + j0 + tx];
    __syncthreads();
    out[(size_t)(4 * (j0 + ty) + g) * K + k0 + tx] = to_tf32(tile[tx][ty]);
}

__global__ void reorder_b_kernel(const float* __restrict__ in, float* __restrict__ out) {
    int n = blockIdx.x * blockDim.x + threadIdx.x;   // 0..4095
    out[n] = in[(n & 3) * HIDDEN + (n >> 2)];
}

// ---------------------------------------------------------------------------
// Pack x: [B, S, I] -> [S*B, I]  (row m = t*B + b), tf32-rounded
// ---------------------------------------------------------------------------
__global__ void pack_x_kernel(const float4* __restrict__ x, float4* __restrict__ xp) {
    int n = blockIdx.x * blockDim.x + threadIdx.x;   // over SB*INPUT/4
    const int I4 = INPUT / 4;
    int k = n % I4;
    int rr = n / I4;
    int b = rr % BATCH;
    int t = rr / BATCH;
    float4 v = x[((size_t)b * SEQ + t) * I4 + k];
    v.x = to_tf32(v.x); v.y = to_tf32(v.y); v.z = to_tf32(v.z); v.w = to_tf32(v.w);
    xp[n] = v;
}

__global__ void zero_state_kernel(float* __restrict__ h1_0, float* __restrict__ c1,
                                  float* __restrict__ c2, float* __restrict__ h2_0) {
    int idx = blockIdx.x * blockDim.x + threadIdx.x;
    if (idx < BATCH * HIDDEN) {
        h1_0[idx] = 0.f; c1[idx] = 0.f; c2[idx] = 0.f; h2_0[idx] = 0.f;
    }
}

// ---------------------------------------------------------------------------
// Final projection (M=256, N=1000, K=1024) — scalar fp32 (exact), small cost
// ---------------------------------------------------------------------------
__global__ void final_proj_kernel(const float* __restrict__ A,
                                  const float* __restrict__ B,
                                  const float* __restrict__ bias,
                                  float* __restrict__ C)
{
    constexpr int BM = 64, BN = 64, BK = 16, TM = 4, TN = 4, TX = 16;
    __shared__ float As[BK][BM];
    __shared__ float Bs[BK][BN];
    const int tid  = threadIdx.x;
    const int tx   = tid % TX;
    const int ty   = tid / TX;
    const int brow = blockIdx.y * BM;
    const int bcol = blockIdx.x * BN;
    float acc[TM][TN] = {};

    for (int kt = 0; kt < HIDDEN; kt += BK) {
        {
            int ar = tid / (BK / 4);
            int ak = (tid % (BK / 4)) * 4;
            float4 v = *reinterpret_cast<const float4*>(A + (size_t)(brow + ar) * HIDDEN + kt + ak);
            As[ak + 0][ar] = v.x; As[ak + 1][ar] = v.y; As[ak + 2][ar] = v.z; As[ak + 3][ar] = v.w;
        }
        {
            int bk = tid / (BN / 4);
            int bn = (tid % (BN / 4)) * 4;
            int col = bcol + bn;
            const float* src = B + (size_t)(kt + bk) * CLASSES + col;
            Bs[bk][bn + 0] = (col + 0 < CLASSES) ? src[0] : 0.f;
            Bs[bk][bn + 1] = (col + 1 < CLASSES) ? src[1] : 0.f;
            Bs[bk][bn + 2] = (col + 2 < CLASSES) ? src[2] : 0.f;
            Bs[bk][bn + 3] = (col + 3 < CLASSES) ? src[3] : 0.f;
        }
        __syncthreads();
        #pragma unroll
        for (int k = 0; k < BK; k++) {
            float ra[TM], rb[TN];
            #pragma unroll
            for (int i = 0; i < TM; i++) ra[i] = As[k][ty * TM + i];
            #pragma unroll
            for (int j = 0; j < TN; j++) rb[j] = Bs[k][tx * TN + j];
            #pragma unroll
            for (int i = 0; i < TM; i++)
                #pragma unroll
                for (int j = 0; j < TN; j++)
                    acc[i][j] += ra[i] * rb[j];
        }
        __syncthreads();
    }
    #pragma unroll
    for (int i = 0; i < TM; i++) {
        int rr = brow + ty * TM + i;
        #pragma unroll
        for (int j = 0; j < TN; j++) {
            int col = bcol + tx * TN + j;
            if (col < CLASSES)
                C[(size_t)rr * CLASSES + col] = acc[i][j] + bias[col];
        }
    }
}

// ---------------------------------------------------------------------------
// Launch
// ---------------------------------------------------------------------------
extern "C" void kernel_launch(void* const* d_in, const int* in_sizes, int n_in,
                              void* d_out, int out_size)
{
    const float* x  = (const float*)d_in[0];
    const float* W1 = (const float*)d_in[1];
    const float* U1 = (const float*)d_in[2];
    const float* b1 = (const float*)d_in[3];
    const float* W2 = (const float*)d_in[4];
    const float* U2 = (const float*)d_in[5];
    const float* b2 = (const float*)d_in[6];
    const float* Wo = (const float*)d_in[7];
    const float* bo = (const float*)d_in[8];
    float* out = (float*)d_out;

    float *X, *Z, *H1, *h2, *c1, *c2, *W1r, *U1T, *W2r, *U2T, *b1r, *b2r;
    cudaGetSymbolAddress((void**)&X,   g_X);
    cudaGetSymbolAddress((void**)&Z,   g_Z);
    cudaGetSymbolAddress((void**)&H1,  g_H1);
    cudaGetSymbolAddress((void**)&h2,  g_h2);
    cudaGetSymbolAddress((void**)&c1,  g_c1);
    cudaGetSymbolAddress((void**)&c2,  g_c2);
    cudaGetSymbolAddress((void**)&W1r, g_W1r);
    cudaGetSymbolAddress((void**)&U1T, g_U1T);
    cudaGetSymbolAddress((void**)&W2r, g_W2r);
    cudaGetSymbolAddress((void**)&U2T, g_U2T);
    cudaGetSymbolAddress((void**)&b1r, g_b1r);
    cudaGetSymbolAddress((void**)&b2r, g_b2r);

    // smem sizes: (BM+BN)*36*4 bytes * 2 stages
    const int SMEM_BIG = (128 + 128) * 36 * 4 * 2;   // 73728
    const int SMEM_REC = (64 + 64) * 36 * 4 * 2;     // 36864
    cudaFuncSetAttribute(mma_gemm<128,128,16,0>, cudaFuncAttributeMaxDynamicSharedMemorySize, SMEM_BIG);
    cudaFuncSetAttribute(mma_gemm<128,128,32,0>, cudaFuncAttributeMaxDynamicSharedMemorySize, SMEM_BIG);
    cudaFuncSetAttribute(mma_gemm<64,64,32,1>,   cudaFuncAttributeMaxDynamicSharedMemorySize, SMEM_REC);

    const size_t BH  = (size_t)BATCH * HIDDEN;   // 262144
    const size_t BG4 = (size_t)BATCH * G4;       // 1048576

    // 0) pack X, zero state, reorder weights
    pack_x_kernel<<<SB * INPUT / 4 / 256, 256>>>((const float4*)x, (float4*)X);
    zero_state_kernel<<<(int)(BH / 256), 256>>>(H1, c1, c2, h2);
    reorder_T_kernel<<<dim3(INPUT / 32, 32, 4),  dim3(32, 32)>>>(W1, W1r, INPUT);
    reorder_T_kernel<<<dim3(HIDDEN / 32, 32, 4), dim3(32, 32)>>>(U1, U1T, HIDDEN);
    reorder_T_kernel<<<dim3(HIDDEN / 32, 32, 4), dim3(32, 32)>>>(W2, W2r, HIDDEN);
    reorder_T_kernel<<<dim3(HIDDEN / 32, 32, 4), dim3(32, 32)>>>(U2, U2T, HIDDEN);
    reorder_b_kernel<<<G4 / 256, 256>>>(b1, b1r);
    reorder_b_kernel<<<G4 / 256, 256>>>(b2, b2r);

    // 1) Z = X @ W1r^T + b1r   [16384, 4096], K=512
    mma_gemm<128,128,16,0><<<dim3(G4 / 128, SB / 128), 256, SMEM_BIG>>>(
        X, INPUT, W1r, b1r, Z, nullptr);

    // 2) layer-1 recurrence (fused GEMM + cell), 256 CTAs/step
    for (int t = 0; t < SEQ; t++) {
        mma_gemm<64,64,32,1><<<dim3(G4 / 64, BATCH / 64), 256, SMEM_REC>>>(
            H1 + (size_t)t * BH, HIDDEN, U1T,
            Z + (size_t)t * BG4, c1, H1 + (size_t)(t + 1) * BH);
    }

    // 3) Z = H1[1..64] @ W2r^T + b2r   [16384, 4096], K=1024
    mma_gemm<128,128,32,0><<<dim3(G4 / 128, SB / 128), 256, SMEM_BIG>>>(
        H1 + BH, HIDDEN, W2r, b2r, Z, nullptr);

    // 4) layer-2 recurrence (double-buffered h2)
    for (int t = 0; t < SEQ; t++) {
        mma_gemm<64,64,32,1><<<dim3(G4 / 64, BATCH / 64), 256, SMEM_REC>>>(
            h2 + (size_t)(t & 1) * BH, HIDDEN, U2T,
            Z + (size_t)t * BG4, c2, h2 + (size_t)((t + 1) & 1) * BH);
    }

    // 5) out = h2[0] @ Wo + bo   [256, 1000], K=1024
    final_proj_kernel<<<dim3((CLASSES + 63) / 64, BATCH / 64), 256>>>(h2, Wo, bo, out);
}

// round 4
// speedup vs baseline: 2.7763x; 1.0391x over previous
#include <cuda_runtime.h>
#include <cstdint>
#include <cstddef>

#define BATCH   256
#define SEQ     64
#define INPUT   512
#define HIDDEN  1024
#define CLASSES 1000
#define SB      (SEQ * BATCH)   // 16384
#define G4      (4 * HIDDEN)    // 4096
#define REC_CTAS 256u

// ---------------------------------------------------------------------------
// Scratch (device globals — no allocations allowed)
// ---------------------------------------------------------------------------
__device__ float g_X  [SB * INPUT];                    // packed [S*B, I], tf32-rounded
__device__ float g_Z  [(size_t)SB * G4];               // pre-activations (reused by both layers)
__device__ float g_H1 [(SEQ + 1) * BATCH * HIDDEN];    // h1 per step (slot 0 = zeros), tf32
__device__ float g_h2 [2 * BATCH * HIDDEN];            // double-buffered layer-2 h, tf32
__device__ float g_W1r[(size_t)G4 * INPUT];            // W1^T gate-interleaved [4096, 512]
__device__ float g_U1T[(size_t)G4 * HIDDEN];           // U1^T gate-interleaved [4096, 1024]
__device__ float g_W2r[(size_t)G4 * HIDDEN];
__device__ float g_U2T[(size_t)G4 * HIDDEN];
__device__ float g_b1r[G4];
__device__ float g_b2r[G4];
__device__ unsigned g_bar1[SEQ];
__device__ unsigned g_bar2[SEQ];

// ---------------------------------------------------------------------------
// Helpers
// ---------------------------------------------------------------------------
__device__ __forceinline__ uint32_t smem_to_u32(const void* p) {
    uint32_t a;
    asm("{ .reg .u64 t; cvta.to.shared.u64 t, %1; cvt.u32.u64 %0, t; }"
        : "=r"(a) : "l"(p));
    return a;
}

__device__ __forceinline__ float to_tf32(float x) {
    uint32_t r;
    asm("cvt.rna.tf32.f32 %0, %1;" : "=r"(r) : "f"(x));
    return __uint_as_float(r);
}

__device__ __forceinline__ void cp_async16(uint32_t smem_dst, const void* gmem_src) {
    asm volatile("cp.async.cg.shared.global [%0], [%1], 16;\n" :: "r"(smem_dst), "l"(gmem_src));
}

__device__ __forceinline__ void mma_tf32_16n8k8(float* d, const uint32_t* a, const uint32_t* b) {
    asm volatile(
        "mma.sync.aligned.m16n8k8.row.col.f32.tf32.tf32.f32 "
        "{%0,%1,%2,%3}, {%4,%5,%6,%7}, {%8,%9}, {%0,%1,%2,%3};"
        : "+f"(d[0]), "+f"(d[1]), "+f"(d[2]), "+f"(d[3])
        : "r"(a[0]), "r"(a[1]), "r"(a[2]), "r"(a[3]), "r"(b[0]), "r"(b[1]));
}

__device__ __forceinline__ float sigf(float x) { return 1.f / (1.f + expf(-x)); }

// ---------------------------------------------------------------------------
// Big GEMM (bias epilogue): C[M,N] = A[M,K] @ Bt[N,K]^T + bias
// 128x128 tile, 8 warps (2x4), BK=32, 2-stage cp.async.
// ---------------------------------------------------------------------------
template<int KT>
__global__ void __launch_bounds__(256)
mma_gemm_bias(const float* __restrict__ A, int lda,
              const float* __restrict__ Bt,
              const float* __restrict__ bias,
              float* __restrict__ C)
{
    constexpr int BM = 128, BN = 128, BK = 32, PAD = 36;
    constexpr int WM = 64, WN = 32, MT = 4, NT = 4;
    constexpr int ASZ = BM * PAD, BSZ = BN * PAD;

    extern __shared__ float sm[];
    const uint32_t sbase = smem_to_u32(sm);

    const int tid  = threadIdx.x;
    const int wid  = tid >> 5;
    const int lane = tid & 31;
    const int wm0  = (wid >> 2) * WM;
    const int wn0  = (wid & 3) * WN;
    const int m0   = blockIdx.y * BM;
    const int n0   = blockIdx.x * BN;
    const int K    = KT * BK;

    float acc[MT][NT][4] = {};

    auto load_stage = [&](int kt, int s) {
        const uint32_t aB = sbase + (uint32_t)s * (ASZ + BSZ) * 4u;
        const uint32_t bB = aB + (uint32_t)ASZ * 4u;
        const float* Ag = A  + (size_t)m0 * lda + kt * BK;
        const float* Bg = Bt + (size_t)n0 * K   + kt * BK;
        #pragma unroll
        for (int i = 0; i < BM * 8 / 256; i++) {
            int cid = tid + i * 256;
            int row = cid >> 3, c = cid & 7;
            cp_async16(aB + (uint32_t)row * (PAD * 4) + c * 16,
                       Ag + (size_t)row * lda + c * 4);
        }
        #pragma unroll
        for (int i = 0; i < BN * 8 / 256; i++) {
            int cid = tid + i * 256;
            int row = cid >> 3, c = cid & 7;
            cp_async16(bB + (uint32_t)row * (PAD * 4) + c * 16,
                       Bg + (size_t)row * K + c * 4);
        }
        asm volatile("cp.async.commit_group;\n");
    };

    const int r  = lane >> 2;
    const int cq = lane & 3;

    load_stage(0, 0);

    #pragma unroll 1
    for (int kt = 0; kt < KT; kt++) {
        const int s = kt & 1;
        if (kt + 1 < KT) {
            load_stage(kt + 1, s ^ 1);
            asm volatile("cp.async.wait_group 1;\n");
        } else {
            asm volatile("cp.async.wait_group 0;\n");
        }
        __syncthreads();

        const float* as_f = sm + s * (ASZ + BSZ);
        const float* bs_f = as_f + ASZ;

        #pragma unroll
        for (int ks = 0; ks < 4; ks++) {
            const int k0 = ks * 8;
            uint32_t af[MT][4], bf[NT][2];
            #pragma unroll
            for (int mt = 0; mt < MT; mt++) {
                const int rr = wm0 + mt * 16 + r;
                af[mt][0] = __float_as_uint(as_f[rr * PAD + k0 + cq]);
                af[mt][1] = __float_as_uint(as_f[(rr + 8) * PAD + k0 + cq]);
                af[mt][2] = __float_as_uint(as_f[rr * PAD + k0 + cq + 4]);
                af[mt][3] = __float_as_uint(as_f[(rr + 8) * PAD + k0 + cq + 4]);
            }
            #pragma unroll
            for (int nt = 0; nt < NT; nt++) {
                const int cc = wn0 + nt * 8 + r;
                bf[nt][0] = __float_as_uint(bs_f[cc * PAD + k0 + cq]);
                bf[nt][1] = __float_as_uint(bs_f[cc * PAD + k0 + cq + 4]);
            }
            #pragma unroll
            for (int mt = 0; mt < MT; mt++)
                #pragma unroll
                for (int nt = 0; nt < NT; nt++)
                    mma_tf32_16n8k8(acc[mt][nt], af[mt], bf[nt]);
        }
        __syncthreads();
    }

    #pragma unroll
    for (int mt = 0; mt < MT; mt++) {
        #pragma unroll
        for (int nt = 0; nt < NT; nt++) {
            const int row  = m0 + wm0 + mt * 16 + r;
            const int colb = n0 + wn0 + nt * 8 + cq * 2;
            float2 bv = *reinterpret_cast<const float2*>(bias + colb);
            float2 o01 = { acc[mt][nt][0] + bv.x, acc[mt][nt][1] + bv.y };
            float2 o23 = { acc[mt][nt][2] + bv.x, acc[mt][nt][3] + bv.y };
            *reinterpret_cast<float2*>(C + (size_t)row * G4 + colb)       = o01;
            *reinterpret_cast<float2*>(C + (size_t)(row + 8) * G4 + colb) = o23;
        }
    }
}

// ---------------------------------------------------------------------------
// Persistent recurrence: one launch does all 64 timesteps of one LSTM layer.
// Grid = (64, 4) = 256 CTAs, co-resident (2/SM). Tile 64x64, BK=32, 2-stage.
// L1 = 1: A_t = Hbuf + t*BH, h_out -> Hbuf + (t+1)*BH (keeps all h1 for GEMM2)
// L1 = 0: double-buffered Hbuf slots (t&1) -> ((t+1)&1)
// c-state lives in registers (each thread owns fixed (row, j) pairs).
// Cross-step h visibility: writes via STG (L2) + threadfence; reads via
// cp.async.cg (L2, bypasses L1). Grid barrier per step on g_bar[t].
// ---------------------------------------------------------------------------
template<int L1>
__global__ void __launch_bounds__(256, 2)
rec_layer(const float* __restrict__ Uw,    // [4096, 1024] gate-interleaved, transposed
          const float* __restrict__ Z,     // [SEQ*BATCH, 4096]
          float* __restrict__ Hbuf,
          unsigned* __restrict__ bar)
{
    constexpr int BM = 64, BN = 64, BK = 32, PAD = 36, KT = 32;
    constexpr int WM = 32, WN = 16, MT = 2, NT = 2;
    constexpr int ASZ = BM * PAD, BSZ = BN * PAD;
    const size_t BH  = (size_t)BATCH * HIDDEN;
    const size_t BG4 = (size_t)BATCH * G4;

    extern __shared__ float sm[];
    const uint32_t sbase = smem_to_u32(sm);

    const int tid  = threadIdx.x;
    const int wid  = tid >> 5;
    const int lane = tid & 31;
    const int wm0  = (wid >> 2) * WM;
    const int wn0  = (wid & 3) * WN;
    const int m0   = blockIdx.y * BM;
    const int n0   = blockIdx.x * BN;

    const int r  = lane >> 2;
    const int cq = lane & 3;

    float creg[MT * NT * 2] = {};    // c-state, persistent across steps (even lanes)

    #pragma unroll 1
    for (int t = 0; t < SEQ; t++) {
        const float* A    = Hbuf + (size_t)(L1 ? t : (t & 1)) * BH;
        float*       Hout = Hbuf + (size_t)(L1 ? (t + 1) : ((t + 1) & 1)) * BH;
        const float* Zt   = Z + (size_t)t * BG4;

        float acc[MT][NT][4] = {};

        auto load_stage = [&](int kt, int s) {
            const uint32_t aB = sbase + (uint32_t)s * (ASZ + BSZ) * 4u;
            const uint32_t bB = aB + (uint32_t)ASZ * 4u;
            const float* Ag = A  + (size_t)m0 * HIDDEN + kt * BK;
            const float* Bg = Uw + (size_t)n0 * HIDDEN + kt * BK;
            #pragma unroll
            for (int i = 0; i < BM * 8 / 256; i++) {
                int cid = tid + i * 256;
                int row = cid >> 3, c = cid & 7;
                cp_async16(aB + (uint32_t)row * (PAD * 4) + c * 16,
                           Ag + (size_t)row * HIDDEN + c * 4);
            }
            #pragma unroll
            for (int i = 0; i < BN * 8 / 256; i++) {
                int cid = tid + i * 256;
                int row = cid >> 3, c = cid & 7;
                cp_async16(bB + (uint32_t)row * (PAD * 4) + c * 16,
                           Bg + (size_t)row * HIDDEN + c * 4);
            }
            asm volatile("cp.async.commit_group;\n");
        };

        load_stage(0, 0);

        #pragma unroll 1
        for (int kt = 0; kt < KT; kt++) {
            const int s = kt & 1;
            if (kt + 1 < KT) {
                load_stage(kt + 1, s ^ 1);
                asm volatile("cp.async.wait_group 1;\n");
            } else {
                asm volatile("cp.async.wait_group 0;\n");
            }
            __syncthreads();

            const float* as_f = sm + s * (ASZ + BSZ);
            const float* bs_f = as_f + ASZ;

            #pragma unroll
            for (int ks = 0; ks < 4; ks++) {
                const int k0 = ks * 8;
                uint32_t af[MT][4], bf[NT][2];
                #pragma unroll
                for (int mt = 0; mt < MT; mt++) {
                    const int rr = wm0 + mt * 16 + r;
                    af[mt][0] = __float_as_uint(as_f[rr * PAD + k0 + cq]);
                    af[mt][1] = __float_as_uint(as_f[(rr + 8) * PAD + k0 + cq]);
                    af[mt][2] = __float_as_uint(as_f[rr * PAD + k0 + cq + 4]);
                    af[mt][3] = __float_as_uint(as_f[(rr + 8) * PAD + k0 + cq + 4]);
                }
                #pragma unroll
                for (int nt = 0; nt < NT; nt++) {
                    const int cc = wn0 + nt * 8 + r;
                    bf[nt][0] = __float_as_uint(bs_f[cc * PAD + k0 + cq]);
                    bf[nt][1] = __float_as_uint(bs_f[cc * PAD + k0 + cq + 4]);
                }
                #pragma unroll
                for (int mt = 0; mt < MT; mt++)
                    #pragma unroll
                    for (int nt = 0; nt < NT; nt++)
                        mma_tf32_16n8k8(acc[mt][nt], af[mt], bf[nt]);
            }
            __syncthreads();
        }

        // ---- fused LSTM cell epilogue ----
        #pragma unroll
        for (int mt = 0; mt < MT; mt++) {
            #pragma unroll
            for (int nt = 0; nt < NT; nt++) {
                const int row  = m0 + wm0 + mt * 16 + r;
                const int colb = n0 + wn0 + nt * 8 + cq * 2;
                float v0 = acc[mt][nt][0], v1 = acc[mt][nt][1];
                float v2 = acc[mt][nt][2], v3 = acc[mt][nt][3];
                float2 z01 = *reinterpret_cast<const float2*>(Zt + (size_t)row * G4 + colb);
                float2 z23 = *reinterpret_cast<const float2*>(Zt + (size_t)(row + 8) * G4 + colb);
                v0 += z01.x; v1 += z01.y; v2 += z23.x; v3 += z23.y;
                // even lanes hold (i, f); partner lane^1 holds (g, o)
                float p0 = __shfl_xor_sync(0xffffffffu, v0, 1);
                float p1 = __shfl_xor_sync(0xffffffffu, v1, 1);
                float p2 = __shfl_xor_sync(0xffffffffu, v2, 1);
                float p3 = __shfl_xor_sync(0xffffffffu, v3, 1);
                if ((lane & 1) == 0) {
                    const int j = colb >> 2;
                    const int ci = (mt * NT + nt) * 2;
                    {
                        float cn = sigf(v1) * creg[ci] + sigf(v0) * tanhf(p0);
                        creg[ci] = cn;
                        Hout[(size_t)row * HIDDEN + j] = to_tf32(sigf(p1) * tanhf(cn));
                    }
                    {
                        float cn = sigf(v3) * creg[ci + 1] + sigf(v2) * tanhf(p2);
                        creg[ci + 1] = cn;
                        Hout[(size_t)(row + 8) * HIDDEN + j] = to_tf32(sigf(p3) * tanhf(cn));
                    }
                }
            }
        }

        // ---- grid barrier between steps ----
        if (t < SEQ - 1) {
            __syncthreads();
            if (tid == 0) {
                __threadfence();
                atomicAdd(&bar[t], 1u);
                volatile unsigned* p = bar + t;
                while (*p < REC_CTAS) { }
                __threadfence();
            }
            __syncthreads();
        }
    }
}

// ---------------------------------------------------------------------------
// Merged weight reorder: z = matrix*4 + gate; out[4j+g, k] = in[k, g*H + j]
// ---------------------------------------------------------------------------
__global__ void reorder_w_all(const float* __restrict__ W1, const float* __restrict__ U1,
                              const float* __restrict__ W2, const float* __restrict__ U2,
                              float* __restrict__ W1r, float* __restrict__ U1T,
                              float* __restrict__ W2r, float* __restrict__ U2T)
{
    __shared__ float tile[32][33];
    const int z  = blockIdx.z;
    const int mi = z >> 2;
    const int g  = z & 3;
    const int K  = (mi == 0) ? INPUT : HIDDEN;
    const int k0 = blockIdx.x * 32;
    if (k0 >= K) return;
    const int j0 = blockIdx.y * 32;
    const float* in  = (mi == 0) ? W1 : (mi == 1) ? U1 : (mi == 2) ? W2 : U2;
    float*       out = (mi == 0) ? W1r : (mi == 1) ? U1T : (mi == 2) ? W2r : U2T;
    const int tx = threadIdx.x, ty = threadIdx.y;
    tile[ty][tx] = in[(size_t)(k0 + ty) * G4 + g * HIDDEN + j0 + tx];
    __syncthreads();
    out[(size_t)(4 * (j0 + ty) + g) * K + k0 + tx] = to_tf32(tile[tx][ty]);
}

__global__ void reorder_b_all(const float* __restrict__ b1, const float* __restrict__ b2,
                              float* __restrict__ b1r, float* __restrict__ b2r)
{
    int n = blockIdx.x * blockDim.x + threadIdx.x;   // 0..8191
    if (n < G4) b1r[n] = b1[(n & 3) * HIDDEN + (n >> 2)];
    else {
        int m = n - G4;
        b2r[m] = b2[(m & 3) * HIDDEN + (m >> 2)];
    }
}

// ---------------------------------------------------------------------------
// Pack x: [B, S, I] -> [S*B, I]  (row m = t*B + b), tf32-rounded
// ---------------------------------------------------------------------------
__global__ void pack_x_kernel(const float4* __restrict__ x, float4* __restrict__ xp) {
    int n = blockIdx.x * blockDim.x + threadIdx.x;
    const int I4 = INPUT / 4;
    int k = n % I4;
    int rr = n / I4;
    int b = rr % BATCH;
    int t = rr / BATCH;
    float4 v = x[((size_t)b * SEQ + t) * I4 + k];
    v.x = to_tf32(v.x); v.y = to_tf32(v.y); v.z = to_tf32(v.z); v.w = to_tf32(v.w);
    xp[n] = v;
}

__global__ void zero_state_kernel(float* __restrict__ h1_0, float* __restrict__ h2_0,
                                  unsigned* __restrict__ bar1, unsigned* __restrict__ bar2) {
    int idx = blockIdx.x * blockDim.x + threadIdx.x;
    if (idx < BATCH * HIDDEN) { h1_0[idx] = 0.f; h2_0[idx] = 0.f; }
    if (idx < SEQ) { bar1[idx] = 0u; bar2[idx] = 0u; }
}

// ---------------------------------------------------------------------------
// Final projection (M=256, N=1000, K=1024) — scalar fp32 (exact)
// ---------------------------------------------------------------------------
__global__ void final_proj_kernel(const float* __restrict__ A,
                                  const float* __restrict__ B,
                                  const float* __restrict__ bias,
                                  float* __restrict__ C)
{
    constexpr int BM = 64, BN = 64, BK = 16, TM = 4, TN = 4, TX = 16;
    __shared__ float As[BK][BM];
    __shared__ float Bs[BK][BN];
    const int tid  = threadIdx.x;
    const int tx   = tid % TX;
    const int ty   = tid / TX;
    const int brow = blockIdx.y * BM;
    const int bcol = blockIdx.x * BN;
    float acc[TM][TN] = {};

    for (int kt = 0; kt < HIDDEN; kt += BK) {
        {
            int ar = tid / (BK / 4);
            int ak = (tid % (BK / 4)) * 4;
            float4 v = *reinterpret_cast<const float4*>(A + (size_t)(brow + ar) * HIDDEN + kt + ak);
            As[ak + 0][ar] = v.x; As[ak + 1][ar] = v.y; As[ak + 2][ar] = v.z; As[ak + 3][ar] = v.w;
        }
        {
            int bk = tid / (BN / 4);
            int bn = (tid % (BN / 4)) * 4;
            int col = bcol + bn;
            const float* src = B + (size_t)(kt + bk) * CLASSES + col;
            Bs[bk][bn + 0] = (col + 0 < CLASSES) ? src[0] : 0.f;
            Bs[bk][bn + 1] = (col + 1 < CLASSES) ? src[1] : 0.f;
            Bs[bk][bn + 2] = (col + 2 < CLASSES) ? src[2] : 0.f;
            Bs[bk][bn + 3] = (col + 3 < CLASSES) ? src[3] : 0.f;
        }
        __syncthreads();
        #pragma unroll
        for (int k = 0; k < BK; k++) {
            float ra[TM], rb[TN];
            #pragma unroll
            for (int i = 0; i < TM; i++) ra[i] = As[k][ty * TM + i];
            #pragma unroll
            for (int j = 0; j < TN; j++) rb[j] = Bs[k][tx * TN + j];
            #pragma unroll
            for (int i = 0; i < TM; i++)
                #pragma unroll
                for (int j = 0; j < TN; j++)
                    acc[i][j] += ra[i] * rb[j];
        }
        __syncthreads();
    }
    #pragma unroll
    for (int i = 0; i < TM; i++) {
        int rr = brow + ty * TM + i;
        #pragma unroll
        for (int j = 0; j < TN; j++) {
            int col = bcol + tx * TN + j;
            if (col < CLASSES)
                C[(size_t)rr * CLASSES + col] = acc[i][j] + bias[col];
        }
    }
}

// ---------------------------------------------------------------------------
// Launch (9 graph nodes; launch #6 = rec_layer<1> for ncu capture)
// ---------------------------------------------------------------------------
extern "C" void kernel_launch(void* const* d_in, const int* in_sizes, int n_in,
                              void* d_out, int out_size)
{
    const float* x  = (const float*)d_in[0];
    const float* W1 = (const float*)d_in[1];
    const float* U1 = (const float*)d_in[2];
    const float* b1 = (const float*)d_in[3];
    const float* W2 = (const float*)d_in[4];
    const float* U2 = (const float*)d_in[5];
    const float* b2 = (const float*)d_in[6];
    const float* Wo = (const float*)d_in[7];
    const float* bo = (const float*)d_in[8];
    float* out = (float*)d_out;

    float *X, *Z, *H1, *h2, *W1r, *U1T, *W2r, *U2T, *b1r, *b2r;
    unsigned *bar1, *bar2;
    cudaGetSymbolAddress((void**)&X,   g_X);
    cudaGetSymbolAddress((void**)&Z,   g_Z);
    cudaGetSymbolAddress((void**)&H1,  g_H1);
    cudaGetSymbolAddress((void**)&h2,  g_h2);
    cudaGetSymbolAddress((void**)&W1r, g_W1r);
    cudaGetSymbolAddress((void**)&U1T, g_U1T);
    cudaGetSymbolAddress((void**)&W2r, g_W2r);
    cudaGetSymbolAddress((void**)&U2T, g_U2T);
    cudaGetSymbolAddress((void**)&b1r, g_b1r);
    cudaGetSymbolAddress((void**)&b2r, g_b2r);
    cudaGetSymbolAddress((void**)&bar1, g_bar1);
    cudaGetSymbolAddress((void**)&bar2, g_bar2);

    const int SMEM_BIG = (128 + 128) * 36 * 4 * 2;   // 73728
    const int SMEM_REC = (64 + 64) * 36 * 4 * 2;     // 36864
    cudaFuncSetAttribute(mma_gemm_bias<16>, cudaFuncAttributeMaxDynamicSharedMemorySize, SMEM_BIG);
    cudaFuncSetAttribute(mma_gemm_bias<32>, cudaFuncAttributeMaxDynamicSharedMemorySize, SMEM_BIG);
    cudaFuncSetAttribute(rec_layer<1>, cudaFuncAttributeMaxDynamicSharedMemorySize, SMEM_REC);
    cudaFuncSetAttribute(rec_layer<0>, cudaFuncAttributeMaxDynamicSharedMemorySize, SMEM_REC);

    const size_t BH = (size_t)BATCH * HIDDEN;

    // 1) reorder weights (one launch)
    reorder_w_all<<<dim3(32, 32, 16), dim3(32, 32)>>>(W1, U1, W2, U2, W1r, U1T, W2r, U2T);
    // 2) reorder biases
    reorder_b_all<<<2 * G4 / 256, 256>>>(b1, b2, b1r, b2r);
    // 3) pack X
    pack_x_kernel<<<SB * INPUT / 4 / 256, 256>>>((const float4*)x, (float4*)X);
    // 4) zero state + barriers
    zero_state_kernel<<<(int)(BH / 256), 256>>>(H1, h2, bar1, bar2);
    // 5) Z = X @ W1r^T + b1r
    mma_gemm_bias<16><<<dim3(G4 / 128, SB / 128), 256, SMEM_BIG>>>(X, INPUT, W1r, b1r, Z);
    // 6) layer-1 recurrence (persistent, all 64 steps)   <-- ncu -s 5 -c 1 captures this
    rec_layer<1><<<dim3(64, 4), 256, SMEM_REC>>>(U1T, Z, H1, bar1);
    // 7) Z = H1[1..64] @ W2r^T + b2r
    mma_gemm_bias<32><<<dim3(G4 / 128, SB / 128), 256, SMEM_BIG>>>(H1 + BH, HIDDEN, W2r, b2r, Z);
    // 8) layer-2 recurrence (persistent)
    rec_layer<0><<<dim3(64, 4), 256, SMEM_REC>>>(U2T, Z, h2, bar2);
    // 9) out = h2[0] @ Wo + bo
    final_proj_kernel<<<dim3((CLASSES + 63) / 64, BATCH / 64), 256>>>(h2, Wo, bo, out);
}